// round 8
// baseline (speedup 1.0000x reference)
#include <cuda_runtime.h>

// x: (B=8, ns=4, D=512, nc=64) fp32
// out: concat(map_hidden, map_mask), each (B, D, 4, 64, 65) fp32.
// For rel in 0..3, base=1<<rel:
//   out[b,d,rel,i,j] = max(x[b,rel,d, i .. i+k-1]) where k=(j-i)/base,
//   valid when i%base==0, (j-i)%base==0, i<j<64. Mask = 1.0 at hits.
//
// Pure store-bound (~545 MB out). Persistent CTAs: each CTA owns one rel
// and NBD=4 bd values. The per-chunk gather-index pattern is bd-invariant,
// so it is computed ONCE into registers (sentinel ZS = shared zero slot),
// then the per-bd write phase is just LDS + compare + STG.128 pairs.

#define B_DIM 8
#define D_DIM 512
#define NC 64
#define NJ 65
#define REGION (4 * NC * NJ)        // 16640 floats per half per (b,d)
#define RELBLK (NC * NJ)            // 4160 floats per rel block
#define NCHK (RELBLK / 4)           // 1040 float4 chunks per rel block
#define NBD 4                       // bd values per CTA
#define ZS 4096                     // zero-slot word index in Sp

template<int REL>
__device__ __forceinline__ void run_rel(
    const float* __restrict__ x, float* __restrict__ out, long half,
    int group, int tid, float* __restrict__ Sp, float* __restrict__ xsh)
{
    constexpr int W   = NC >> REL;      // table rows / row width
    constexpr int BM  = (1 << REL) - 1;
    constexpr int BLK = REL * RELBLK;

    // ---- control words (bd-invariant): Sp word-indices, ZS = miss ----
    int cidx[5][4];
    #pragma unroll
    for (int it = 0; it < 5; it++) {
        int qq = tid + it * 256;
        #pragma unroll
        for (int l = 0; l < 4; l++) cidx[it][l] = ZS;
        if (qq < NCHK) {
            int er = qq << 2;
            int i  = er / 65;           // const divisor -> mulhi
            int j  = er - i * 65;
            #pragma unroll
            for (int l = 0; l < 4; l++) {
                int jj = j + l, ii = i;
                if (jj >= NJ) { jj -= NJ; ii++; }      // one row wrap max
                int diff = jj - ii;
                bool hit = (diff > 0) & (jj < NC);
                if (REL > 0) hit = hit & (((ii | diff) & BM) == 0);
                if (hit) cidx[it][l] = (ii >> REL) * W + (diff >> REL) - 1;
            }
        }
    }

    if (tid == 0) Sp[ZS] = 0.0f;        // builds never touch word ZS

    for (int t = 0; t < NBD; t++) {
        const int bd = group * NBD + t;
        const int b  = bd >> 9;
        const int d  = bd & 511;

        __syncthreads();                // prev write phase done reading Sp
        if (tid < NC)
            xsh[tid] = x[(((b << 2) + REL) * D_DIM + d) * NC + tid];
        __syncthreads();

        // ---- build running-max table for this bd ----
        if (tid < W) {
            int i  = tid << REL;
            int bo = tid * W;
            int emax = (i + W < NC) ? (i + W) : NC;
            float m = xsh[i];
            Sp[bo] = m;
            #pragma unroll 4
            for (int e = i + 1; e < emax; e++) {
                m = fmaxf(m, xsh[e]);
                Sp[bo + (e - i)] = m;
            }
        }
        __syncthreads();

        // ---- write phase: register-held control, lean lanes ----
        float* __restrict__ hid = out + (long)bd * REGION + BLK + (tid << 2);
        float* __restrict__ msk = hid + half;

        #pragma unroll
        for (int it = 0; it < 5; it++) {
            if (it == 4 && tid >= 16) break;      // chunks 1024..1039
            float4 h, m;
            h.x = Sp[cidx[it][0]];  m.x = (cidx[it][0] != ZS) ? 1.0f : 0.0f;
            h.y = Sp[cidx[it][1]];  m.y = (cidx[it][1] != ZS) ? 1.0f : 0.0f;
            h.z = Sp[cidx[it][2]];  m.z = (cidx[it][2] != ZS) ? 1.0f : 0.0f;
            h.w = Sp[cidx[it][3]];  m.w = (cidx[it][3] != ZS) ? 1.0f : 0.0f;
            *reinterpret_cast<float4*>(hid + it * 1024) = h;
            *reinterpret_cast<float4*>(msk + it * 1024) = m;
        }
    }
}

__global__ __launch_bounds__(256, 4)
void prop3d_kernel(const float* __restrict__ x, float* __restrict__ out,
                   long half_elems) {
    __shared__ float xsh[NC];
    __shared__ float Sp[ZS + 1];        // 64x64 worst case + zero slot

    const int bid   = blockIdx.x;
    const int rel   = bid & 3;
    const int group = bid >> 2;         // 0 .. 1023, each covers NBD bd's
    const int tid   = threadIdx.x;

    switch (rel) {
        case 0:  run_rel<0>(x, out, half_elems, group, tid, Sp, xsh); break;
        case 1:  run_rel<1>(x, out, half_elems, group, tid, Sp, xsh); break;
        case 2:  run_rel<2>(x, out, half_elems, group, tid, Sp, xsh); break;
        default: run_rel<3>(x, out, half_elems, group, tid, Sp, xsh); break;
    }
}

extern "C" void kernel_launch(void* const* d_in, const int* in_sizes, int n_in,
                              void* d_out, int out_size) {
    const float* x = (const float*)d_in[0];
    float* out = (float*)d_out;
    long half = (long)out_size / 2;     // map_hidden elements; map_mask follows

    prop3d_kernel<<<(B_DIM * D_DIM / NBD) * 4, 256>>>(x, out, half);
}

// round 9
// speedup vs baseline: 1.1432x; 1.1432x over previous
#include <cuda_runtime.h>

// x: (B=8, ns=4, D=512, nc=64) fp32
// out: concat(map_hidden, map_mask), each (B, D, 4, 64, 65) fp32.
// For rel in 0..3, base=1<<rel:
//   out[b,d,rel,i,j] = max(x[b,rel,d, i .. i+k-1]) where k=(j-i)/base,
//   valid when i%base==0, (j-i)%base==0, i<j<64. Mask = 1.0 at hits.
//
// Pure store-bound (~545 MB out). Grid = bd x rel x half-row-block:
// 32768 CTAs, each writes rows i in [32h, 32h+32) of one rel block
// (520 float4 chunks x {hidden,mask}). Fused h+m stores amortize the
// per-chunk control math; (i,j) updated incrementally (no division).

#define B_DIM 8
#define D_DIM 512
#define NC 64
#define NJ 65
#define REGION (4 * NC * NJ)        // 16640 floats per half per (b,d)
#define RELBLK (NC * NJ)            // 4160 floats per rel block
#define HCHK 520                    // float4 chunks per half-row-block

template<int REL>
__device__ __forceinline__ void run_half(
    const float* __restrict__ xrow,   // x[b, REL, d, :]
    float* __restrict__ hid,          // out + bd*REGION + REL*RELBLK
    float* __restrict__ msk,          // hid + half_elems
    float* __restrict__ Sp,           // shared, (W/2)*W words
    float* __restrict__ xsh,          // shared, 64 words
    int h, int tid)
{
    constexpr int W  = NC >> REL;     // table row width
    constexpr int HR = W >> 1;        // table rows this CTA needs
    constexpr int BM = (1 << REL) - 1;

    // ---- stage input row (need e in [i, i+W) for i in [32h, 32h+32)) ----
    if (tid < NC) xsh[tid] = xrow[tid];
    __syncthreads();

    // ---- build running-max rows r = 0..HR-1, i = (h*HR + r)<<REL ----
    if (tid < HR) {
        int i  = (h * HR + tid) << REL;
        int bo = tid * W;
        int emax = (i + W < NC) ? (i + W) : NC;
        float m = xsh[i];
        Sp[bo] = m;
        #pragma unroll 4
        for (int e = i + 1; e < emax; e++) {
            m = fmaxf(m, xsh[e]);
            Sp[bo + (e - i)] = m;
        }
    }
    __syncthreads();

    // ---- write loop: 520 chunks, rows i = 32h + il, il in [0,32) ----
    // er_local = 4q; il = er_local/65, j = er_local%65, updated incrementally.
    int q  = tid;
    int il = (tid << 2) / 65;
    int j  = (tid << 2) - il * 65;
    const int ibase = h << 5;                 // 32h

    while (q < HCHK) {
        float4 hv4, mv4;
        float* hp = reinterpret_cast<float*>(&hv4);
        float* mp = reinterpret_cast<float*>(&mv4);

        #pragma unroll
        for (int l = 0; l < 4; l++) {
            int jj = j + l;
            int li = il;
            if (jj >= NJ) { jj -= NJ; li += 1; }      // one row wrap max
            int ii   = ibase + li;
            int diff = jj - ii;
            bool hit = (diff > 0) & (jj < NC);
            if (REL > 0) hit = hit & (((ii | diff) & BM) == 0);
            float hv = 0.0f, mv = 0.0f;
            if (hit) {
                hv = Sp[(li >> REL) * W + (diff >> REL) - 1];
                mv = 1.0f;
            }
            hp[l] = hv;
            mp[l] = mv;
        }

        int off = (ibase * NJ) + (q << 2);
        *reinterpret_cast<float4*>(hid + off) = hv4;
        *reinterpret_cast<float4*>(msk + off) = mv4;

        // advance by 256 chunks = 1024 elements = 15 rows + 49
        q  += 256;
        il += 15; j += 49;
        if (j >= NJ) { j -= NJ; il += 1; }
    }
}

__global__ __launch_bounds__(256, 1)
void prop3d_kernel(const float* __restrict__ x, float* __restrict__ out,
                   long half_elems) {
    __shared__ float xsh[NC];
    __shared__ float Sp[2048];          // worst case REL=0: 32 rows x 64 (8 KB)

    const int bid = blockIdx.x;
    const int rel = bid & 3;
    const int h   = (bid >> 2) & 1;     // which 32-row half of the rel block
    const int bd  = bid >> 3;           // b*512 + d
    const int b   = bd >> 9;
    const int d   = bd & 511;
    const int tid = threadIdx.x;

    const float* xrow = x + (((long)((b << 2) + rel) * D_DIM) + d) * NC;
    float* hid = out + (long)bd * REGION + rel * RELBLK;
    float* msk = hid + half_elems;

    switch (rel) {
        case 0:  run_half<0>(xrow, hid, msk, Sp, xsh, h, tid); break;
        case 1:  run_half<1>(xrow, hid, msk, Sp, xsh, h, tid); break;
        case 2:  run_half<2>(xrow, hid, msk, Sp, xsh, h, tid); break;
        default: run_half<3>(xrow, hid, msk, Sp, xsh, h, tid); break;
    }
}

extern "C" void kernel_launch(void* const* d_in, const int* in_sizes, int n_in,
                              void* d_out, int out_size) {
    const float* x = (const float*)d_in[0];
    float* out = (float*)d_out;
    long half = (long)out_size / 2;     // map_hidden elements; map_mask follows

    prop3d_kernel<<<B_DIM * D_DIM * 4 * 2, 256>>>(x, out, half);
}